// round 16
// baseline (speedup 1.0000x reference)
#include <cuda_runtime.h>
#include <cuda_fp16.h>
#include <cstdint>

#define F        128
#define N_ATOMS  8192
#define TILEB    32768        // weight tile: 128 rows * 256B (fp16, swizzled)

#define PTHREADS 256          // pair kernel: 2 CTAs/SM
#define ATHREADS 512          // atom kernels: 1 CTA/SM
#define PTILE    32           // pair tile rows
#define ATILE    64           // atom tile rows

// ---------------------------------------------------------------------------
// Device-global scratch (no allocations allowed)
// ---------------------------------------------------------------------------
__device__ float g_PS[N_ATOMS * F];   // segment-summed pair activations
__device__ float g_AA[N_ATOMS * F];   // atom layer-1 output
// Prepped weights: fp16 (round-to-nearest), B-orientation [n][k], 256B rows,
// XOR-swizzled chunks. 8 tiles of 32768B:
//  0:W2a 1:W2b  2:W1a 3:W1b  4:W3a_c0 5:W3b_c0  6:W3a_c1 7:W3b_c1
__device__ __align__(256) unsigned char g_Wp[8 * TILEB];

// ---- pair kernel SMEM (per CTA, 2 CTAs/SM) ----
//  [0,65536)       W2a, W2b (2 x 32KB) -- read once for fragment hoist
//  [65536,73728)   X buf0 fp16 (32 rows x 256B)
//  [73728,81920)   X buf1
//  [81920,98304)   fp32 stage (32 x 128 fp32 = 16KB)
//  [98304,99840)   bias: ba[128], bb[128], t[128]
#define P_X0     65536
#define P_X1     73728
#define P_STG    81920
#define P_BIAS   98304
#define P_SMEM   99840

// ---- atom kernel SMEM (1 CTA/SM) ----
#define A_X0     65536
#define A_BIAS   81920
#define A_SMEM   83456

// ---------------------------------------------------------------------------
// PTX helpers
// ---------------------------------------------------------------------------
__device__ __forceinline__ uint32_t smem_u32(const void* p) {
    uint32_t a;
    asm("{ .reg .u64 t; cvta.to.shared.u64 t, %1; cvt.u32.u64 %0, t; }" : "=r"(a) : "l"(p));
    return a;
}
__device__ __forceinline__ void ldmx4(uint32_t* r, uint32_t addr) {
    asm volatile("ldmatrix.sync.aligned.m8n8.x4.shared.b16 {%0,%1,%2,%3}, [%4];"
                 : "=r"(r[0]), "=r"(r[1]), "=r"(r[2]), "=r"(r[3]) : "r"(addr));
}
__device__ __forceinline__ void mma16816(float* d, const uint32_t* a, uint32_t b0, uint32_t b1) {
    asm volatile(
        "mma.sync.aligned.m16n8k16.row.col.f32.f16.f16.f32 "
        "{%0,%1,%2,%3}, {%4,%5,%6,%7}, {%8,%9}, {%0,%1,%2,%3};"
        : "+f"(d[0]), "+f"(d[1]), "+f"(d[2]), "+f"(d[3])
        : "r"(a[0]), "r"(a[1]), "r"(a[2]), "r"(a[3]), "r"(b0), "r"(b1));
}
__device__ __forceinline__ void red_v2(float* addr, float a, float b) {
    asm volatile("red.global.add.v2.f32 [%0], {%1,%2};"
                 :: "l"(addr), "f"(a), "f"(b) : "memory");
}
__device__ __forceinline__ void cpa16(uint32_t saddr, const void* g) {
    asm volatile("cp.async.cg.shared.global [%0], [%1], 16;" :: "r"(saddr), "l"(g));
}
__device__ __forceinline__ void cpa_commit() {
    asm volatile("cp.async.commit_group;" ::: "memory");
}
__device__ __forceinline__ void cpa_wait0() {
    asm volatile("cp.async.wait_group 0;" ::: "memory");
}

// ---------------------------------------------------------------------------
// X element store: fp32 float4 -> fp16 at swizzled (row m, k4).
// i = float4 index: m = i>>5, k4 = (i&31)*4. 256B rows; chunk c at (c^(m&7)).
// ---------------------------------------------------------------------------
union H2U { __half2 h; uint32_t u; };

__device__ __forceinline__ void x_store(char* sm, uint32_t x_off, int i, float4 v) {
    const int m = i >> 5, k4 = (i & 31) << 2;
    const uint32_t sw = (uint32_t)(m << 8) + ((uint32_t)(((k4 >> 3) ^ (m & 7))) << 4)
                      + ((uint32_t)((k4 >> 2) & 1) << 3);
    H2U a, b;
    a.h = __floats2half2_rn(v.x, v.y);
    b.h = __floats2half2_rn(v.z, v.w);
    *(uint2*)(sm + x_off + sw) = make_uint2(a.u, b.u);
}

// ---------------------------------------------------------------------------
// Atom-kernel GEMM core (unchanged R15): warp patch 32x16, B from smem.
// ---------------------------------------------------------------------------
__device__ __forceinline__ void gemm_core(uint32_t wBase, uint32_t X,
                                          int mBase, int nBase, int r, int q,
                                          float (&accA)[2][2][4], float (&accB)[2][2][4]) {
    const int cA = q >> 1, cB = q & 1;
    const uint32_t aRow0 = (uint32_t)(mBase + r + 8 * (q & 1));
    const uint32_t bRow  = (uint32_t)(nBase + r + 8 * (q >> 1));

    uint32_t Ah[2][2][4];
    uint32_t Ba[2][4], Bb[2][4];

#define LD_K(buf, kc) do {                                                   \
    const uint32_t oA = (uint32_t)(((cA + (kc)) ^ r) << 4);                  \
    ldmx4(Ah[buf][0], X + (aRow0 << 8) + oA);                                \
    ldmx4(Ah[buf][1], X + ((aRow0 + 16) << 8) + oA);                         \
    const uint32_t oB = (bRow << 8) + (uint32_t)(((cB + (kc)) ^ r) << 4);    \
    ldmx4(Ba[buf], wBase + oB);                                              \
    ldmx4(Bb[buf], wBase + 32768 + oB);                                      \
} while (0)

    LD_K(0, 0);
#pragma unroll
    for (int k = 0; k < 8; k++) {
        const int cur = k & 1;
        if (k < 7) LD_K(cur ^ 1, 2 * (k + 1));
#pragma unroll
        for (int mi = 0; mi < 2; mi++)
#pragma unroll
            for (int jj = 0; jj < 2; jj++) {
                mma16816(accA[mi][jj], Ah[cur][mi], Ba[cur][2 * jj], Ba[cur][2 * jj + 1]);
                mma16816(accB[mi][jj], Ah[cur][mi], Bb[cur][2 * jj], Bb[cur][2 * jj + 1]);
            }
    }
#undef LD_K
}

// ---------------------------------------------------------------------------
// Weight prep (+ zero g_PS): fp16 rn, B-orientation, swizzled. 512x256.
// ---------------------------------------------------------------------------
extern "C" __global__ void eaw_prep(const float* __restrict__ W1a, const float* __restrict__ W1b,
                                    const float* __restrict__ W2a, const float* __restrict__ W2b,
                                    const float* __restrict__ W3a, const float* __restrict__ W3b) {
    const int e = blockIdx.x * blockDim.x + threadIdx.x;
    ((float4*)g_PS)[e]          = make_float4(0.f, 0.f, 0.f, 0.f);
    ((float4*)g_PS)[e + 131072] = make_float4(0.f, 0.f, 0.f, 0.f);

    int mat, off;
    if (e < 65536) { mat = e >> 14; off = e & 16383; }
    else           { int e2 = e - 65536; mat = 4 + (e2 >> 15); off = e2 & 32767; }
    const float* W;
    switch (mat) {
        case 0: W = W2a; break; case 1: W = W2b; break;
        case 2: W = W1a; break; case 3: W = W1b; break;
        case 4: W = W3a; break; default: W = W3b; break;
    }
    const int n = off & 127, k = off >> 7;     // W[k][n] at W[off] (coalesced)
    const __half h = __float2half_rn(W[off]);
    const int p = k >> 7, kk = k & 127;
    int tileIdx;
    switch (mat) {
        case 0: tileIdx = 0; break; case 1: tileIdx = 1; break;
        case 2: tileIdx = 2; break; case 3: tileIdx = 3; break;
        case 4: tileIdx = 4 + 2 * p; break;
        default: tileIdx = 5 + 2 * p; break;
    }
    const size_t pos = ((size_t)n << 8) + ((size_t)((kk >> 3) ^ (n & 7)) << 4) + ((size_t)(kk & 7) << 1);
    *(__half*)(g_Wp + (size_t)tileIdx * TILEB + pos) = h;
}

// ---------------------------------------------------------------------------
// Pair branch: persistent, 32-row tiles, 256 threads (8 warps x patch 32x16),
// 2 CTAs/SM. ALL weight fragments hoisted to registers (64/thread); mainloop
// does only A-ldsm + HMMA. X via cp.async stage; ONE barrier per tile.
// ---------------------------------------------------------------------------
extern "C" __global__ void __launch_bounds__(PTHREADS, 2)
eaw_pair_mm(const float* __restrict__ FP, const int* __restrict__ split,
            const float* __restrict__ b2a, const float* __restrict__ b2b,
            const float* __restrict__ t2, int nTiles) {
    extern __shared__ __align__(1024) char sm[];
    const int tid = threadIdx.x;
    const uint32_t smb = smem_u32(sm);

    {   // weights: 2 tiles (65536B)
        const uint4* src = (const uint4*)g_Wp;
        uint4* dst = (uint4*)sm;
        for (int i = tid; i < 4096; i += PTHREADS) dst[i] = src[i];
    }
    if (tid < 128) {
        ((float*)(sm + P_BIAS))[tid]       = b2a[tid];
        ((float*)(sm + P_BIAS))[128 + tid] = b2b[tid];
        ((float*)(sm + P_BIAS))[256 + tid] = t2[tid];
    }
    __syncthreads();

    const int lane = tid & 31, w = tid >> 5;
    const int nBase = w * 16;                 // 8 warps cover 128 cols
    const int q = lane >> 3, r = lane & 7;
    const float* biasA = (const float*)(sm + P_BIAS);
    const float* biasB = biasA + 128;
    const float* tvv   = biasA + 256;
    const int grid = gridDim.x;

    // hoist ALL weight fragments into registers (once)
    uint32_t Ba[8][4], Bb[8][4];
    {
        const int cB = q & 1;
        const uint32_t bRow = (uint32_t)(nBase + r + 8 * (q >> 1));
#pragma unroll
        for (int k = 0; k < 8; k++) {
            const uint32_t oB = (bRow << 8) + (uint32_t)(((cB + 2 * k) ^ r) << 4);
            ldmx4(Ba[k], smb + oB);
            ldmx4(Bb[k], smb + 32768 + oB);
        }
    }

    const int cA = q >> 1;
    const uint32_t aRow0 = (uint32_t)(r + 8 * (q & 1));
    const uint32_t xOff[2] = {P_X0, P_X1};

    // prologue: X(tile0) direct to buf0; stage fetch X(tile0+grid)
    int tile = blockIdx.x;
    {
        const float4* src = (const float4*)(FP + (size_t)tile * (PTILE * F));
#pragma unroll
        for (int qq = 0; qq < 4; qq++) {
            const int i = tid + qq * PTHREADS;
            x_store(sm, P_X0, i, src[i]);
        }
    }
    if (tile + grid < nTiles) {
        const float* src = FP + (size_t)(tile + grid) * (PTILE * F);
#pragma unroll
        for (int qq = 0; qq < 4; qq++) {
            const int sidx = tid + qq * PTHREADS;
            cpa16(smb + P_STG + (uint32_t)sidx * 16, src + (size_t)sidx * 4);
        }
        cpa_commit();
    }
    __syncthreads();

    int b = 0;
    for (; tile < nTiles; tile += grid) {
        // atom indices (hidden under gemm)
        const int* sp = split + tile * PTILE;
        int atomIdx[2][2];
#pragma unroll
        for (int mi = 0; mi < 2; mi++)
#pragma unroll
            for (int sub = 0; sub < 2; sub++)
                atomIdx[mi][sub] = sp[16 * mi + (lane >> 2) + 8 * sub];

        float accA[2][2][4], accB[2][2][4];
#pragma unroll
        for (int mi = 0; mi < 2; mi++)
#pragma unroll
            for (int jj = 0; jj < 2; jj++)
#pragma unroll
                for (int kq = 0; kq < 4; kq++) { accA[mi][jj][kq] = 0.f; accB[mi][jj][kq] = 0.f; }

        // mainloop: A-ldsm + HMMA only (weights in registers)
        {
            const uint32_t X = smb + xOff[b];
#pragma unroll
            for (int k = 0; k < 8; k++) {
                const uint32_t oA = (uint32_t)(((cA + 2 * k) ^ r) << 4);
                uint32_t A0[4], A1[4];
                ldmx4(A0, X + (aRow0 << 8) + oA);
                ldmx4(A1, X + ((aRow0 + 16) << 8) + oA);
#pragma unroll
                for (int jj = 0; jj < 2; jj++) {
                    mma16816(accA[0][jj], A0, Ba[k][2 * jj], Ba[k][2 * jj + 1]);
                    mma16816(accA[1][jj], A1, Ba[k][2 * jj], Ba[k][2 * jj + 1]);
                    mma16816(accB[0][jj], A0, Bb[k][2 * jj], Bb[k][2 * jj + 1]);
                    mma16816(accB[1][jj], A1, Bb[k][2 * jj], Bb[k][2 * jj + 1]);
                }
            }
        }

        // epilogue right after gemm (overlaps co-resident CTA's gemm)
#pragma unroll
        for (int mi = 0; mi < 2; mi++)
#pragma unroll
            for (int sub = 0; sub < 2; sub++) {
                float* dst = g_PS + (size_t)atomIdx[mi][sub] * F;
#pragma unroll
                for (int jj = 0; jj < 2; jj++) {
                    const int c = nBase + 8 * jj + 2 * (lane & 3);
                    const float v0 = fmaxf(tvv[c]     * (accA[mi][jj][2 * sub]     + biasA[c])     * (accB[mi][jj][2 * sub]     + biasB[c]),     0.f);
                    const float v1 = fmaxf(tvv[c + 1] * (accA[mi][jj][2 * sub + 1] + biasA[c + 1]) * (accB[mi][jj][2 * sub + 1] + biasB[c + 1]), 0.f);
                    red_v2(dst + c, v0, v1);
                }
            }

        const int nt = tile + grid;
        if (nt < nTiles) {
            cpa_wait0();                    // stage holds X(nt) (own bytes)
            const float4* st = (const float4*)(sm + P_STG);
#pragma unroll
            for (int qq = 0; qq < 4; qq++) {
                const int sidx = tid + qq * PTHREADS;
                x_store(sm, xOff[b ^ 1], sidx, st[sidx]);
            }
        }
        __syncthreads();                    // publishes buf b^1; stage LDS done
        if (nt + grid < nTiles) {
            const float* src = FP + (size_t)(nt + grid) * (PTILE * F);
#pragma unroll
            for (int qq = 0; qq < 4; qq++) {
                const int sidx = tid + qq * PTHREADS;
                cpa16(smb + P_STG + (uint32_t)sidx * 16, src + (size_t)sidx * 4);
            }
            cpa_commit();
        }
        b ^= 1;
    }
}

// ---------------------------------------------------------------------------
// Atom layer 1: g_AA = relu(t1*(FA@W1a+b1a)*(FA@W1b+b1b)). 128 CTAs x 64 rows.
// ---------------------------------------------------------------------------
extern "C" __global__ void __launch_bounds__(ATHREADS, 1)
eaw_atom1_mm(const float* __restrict__ FA,
             const float* __restrict__ b1a, const float* __restrict__ b1b,
             const float* __restrict__ t1) {
    extern __shared__ __align__(1024) char sm[];
    const int tid = threadIdx.x;
    const uint32_t smb = smem_u32(sm);
    {
        const uint4* src = (const uint4*)(g_Wp + 2 * TILEB);
        uint4* dst = (uint4*)sm;
        for (int i = tid; i < 4096; i += ATHREADS) dst[i] = src[i];
    }
    if (tid < 128) {
        ((float*)(sm + A_BIAS))[tid]       = b1a[tid];
        ((float*)(sm + A_BIAS))[128 + tid] = b1b[tid];
        ((float*)(sm + A_BIAS))[256 + tid] = t1[tid];
    }
    {
        const float4* src = (const float4*)(FA + (size_t)blockIdx.x * (ATILE * F));
        float4 xv[4];
#pragma unroll
        for (int qq = 0; qq < 4; qq++) xv[qq] = src[tid + qq * ATHREADS];
#pragma unroll
        for (int qq = 0; qq < 4; qq++) x_store(sm, A_X0, tid + qq * ATHREADS, xv[qq]);
    }
    __syncthreads();

    const int lane = tid & 31, w = tid >> 5;
    const int mBase = (w >> 3) * 32, nBase = (w & 7) * 16;
    const int q = lane >> 3, r = lane & 7;
    const float* biasA = (const float*)(sm + A_BIAS);
    const float* biasB = biasA + 128;
    const float* tvv   = biasA + 256;

    float accA[2][2][4], accB[2][2][4];
#pragma unroll
    for (int mi = 0; mi < 2; mi++)
#pragma unroll
        for (int jj = 0; jj < 2; jj++)
#pragma unroll
            for (int kq = 0; kq < 4; kq++) { accA[mi][jj][kq] = 0.f; accB[mi][jj][kq] = 0.f; }

    gemm_core(smb, smb + A_X0, mBase, nBase, r, q, accA, accB);

    float* base = g_AA + (size_t)blockIdx.x * (ATILE * F);
#pragma unroll
    for (int mi = 0; mi < 2; mi++)
#pragma unroll
        for (int sub = 0; sub < 2; sub++) {
            const int row = mBase + 16 * mi + (lane >> 2) + 8 * sub;
#pragma unroll
            for (int jj = 0; jj < 2; jj++) {
                const int c = nBase + 8 * jj + 2 * (lane & 3);
                float2 v;
                v.x = fmaxf(tvv[c]     * (accA[mi][jj][2 * sub]     + biasA[c])     * (accB[mi][jj][2 * sub]     + biasB[c]),     0.f);
                v.y = fmaxf(tvv[c + 1] * (accA[mi][jj][2 * sub + 1] + biasA[c + 1]) * (accB[mi][jj][2 * sub + 1] + biasB[c + 1]), 0.f);
                *(float2*)(base + (size_t)row * F + c) = v;
            }
        }
}

// ---------------------------------------------------------------------------
// Final layer (K=256, two phases): out = relu(t3*([AA|PS]@W3a+b3a)*(...b)).
// 128 CTAs x 64 rows.
// ---------------------------------------------------------------------------
extern "C" __global__ void __launch_bounds__(ATHREADS, 1)
eaw_atom2_mm(const float* __restrict__ b3a, const float* __restrict__ b3b,
             const float* __restrict__ t3, float* __restrict__ out) {
    extern __shared__ __align__(1024) char sm[];
    const int tid = threadIdx.x;
    const uint32_t smb = smem_u32(sm);
    if (tid < 128) {
        ((float*)(sm + A_BIAS))[tid]       = b3a[tid];
        ((float*)(sm + A_BIAS))[128 + tid] = b3b[tid];
        ((float*)(sm + A_BIAS))[256 + tid] = t3[tid];
    }
    const int lane = tid & 31, w = tid >> 5;
    const int mBase = (w >> 3) * 32, nBase = (w & 7) * 16;
    const int q = lane >> 3, r = lane & 7;
    const float* biasA = (const float*)(sm + A_BIAS);
    const float* biasB = biasA + 128;
    const float* tvv   = biasA + 256;

    float accA[2][2][4], accB[2][2][4];
#pragma unroll
    for (int mi = 0; mi < 2; mi++)
#pragma unroll
        for (int jj = 0; jj < 2; jj++)
#pragma unroll
            for (int kq = 0; kq < 4; kq++) { accA[mi][jj][kq] = 0.f; accB[mi][jj][kq] = 0.f; }

#pragma unroll 1
    for (int p = 0; p < 2; p++) {
        if (p) __syncthreads();             // previous phase's smem reads done
        {
            const uint4* src = (const uint4*)(g_Wp + (size_t)(4 + 2 * p) * TILEB);
            uint4* dst = (uint4*)sm;
            for (int i = tid; i < 4096; i += ATHREADS) dst[i] = src[i];
        }
        {
            const float4* src = (const float4*)((p == 0 ? g_AA : g_PS) + (size_t)blockIdx.x * (ATILE * F));
            float4 xv[4];
#pragma unroll
            for (int qq = 0; qq < 4; qq++) xv[qq] = src[tid + qq * ATHREADS];
#pragma unroll
            for (int qq = 0; qq < 4; qq++) x_store(sm, A_X0, tid + qq * ATHREADS, xv[qq]);
        }
        __syncthreads();
        gemm_core(smb, smb + A_X0, mBase, nBase, r, q, accA, accB);
    }

    float* base = out + (size_t)blockIdx.x * (ATILE * F);
#pragma unroll
    for (int mi = 0; mi < 2; mi++)
#pragma unroll
        for (int sub = 0; sub < 2; sub++) {
            const int row = mBase + 16 * mi + (lane >> 2) + 8 * sub;
#pragma unroll
            for (int jj = 0; jj < 2; jj++) {
                const int c = nBase + 8 * jj + 2 * (lane & 3);
                float2 v;
                v.x = fmaxf(tvv[c]     * (accA[mi][jj][2 * sub]     + biasA[c])     * (accB[mi][jj][2 * sub]     + biasB[c]),     0.f);
                v.y = fmaxf(tvv[c + 1] * (accA[mi][jj][2 * sub + 1] + biasA[c + 1]) * (accB[mi][jj][2 * sub + 1] + biasB[c + 1]), 0.f);
                *(float2*)(base + (size_t)row * F + c) = v;
            }
        }
}

// ---------------------------------------------------------------------------
// Launch
// ---------------------------------------------------------------------------
extern "C" void kernel_launch(void* const* d_in, const int* in_sizes, int n_in,
                              void* d_out, int out_size) {
    const float* FA  = (const float*)d_in[0];
    const float* FP  = (const float*)d_in[1];
    const int*   sp  = (const int*)  d_in[2];
    const float* W1a = (const float*)d_in[3];
    const float* b1a = (const float*)d_in[4];
    const float* W1b = (const float*)d_in[5];
    const float* b1b = (const float*)d_in[6];
    const float* t1  = (const float*)d_in[7];
    const float* W2a = (const float*)d_in[8];
    const float* b2a = (const float*)d_in[9];
    const float* W2b = (const float*)d_in[10];
    const float* b2b = (const float*)d_in[11];
    const float* t2  = (const float*)d_in[12];
    const float* W3a = (const float*)d_in[13];
    const float* b3a = (const float*)d_in[14];
    const float* W3b = (const float*)d_in[15];
    const float* b3b = (const float*)d_in[16];
    const float* t3  = (const float*)d_in[17];
    float* out = (float*)d_out;

    const int nPairs    = in_sizes[1] / F;              // 524288
    const int pairTiles = nPairs / PTILE;               // 16384
    const int atomTiles = (in_sizes[0] / F) / ATILE;    // 128

    cudaFuncSetAttribute(eaw_pair_mm,  cudaFuncAttributeMaxDynamicSharedMemorySize, P_SMEM);
    cudaFuncSetAttribute(eaw_atom1_mm, cudaFuncAttributeMaxDynamicSharedMemorySize, A_SMEM);
    cudaFuncSetAttribute(eaw_atom2_mm, cudaFuncAttributeMaxDynamicSharedMemorySize, A_SMEM);

    int nsm = 148;
    cudaDeviceGetAttribute(&nsm, cudaDevAttrMultiProcessorCount, 0);

    eaw_prep<<<512, 256>>>(W1a, W1b, W2a, W2b, W3a, W3b);
    eaw_pair_mm<<<2 * nsm, PTHREADS, P_SMEM>>>(FP, sp, b2a, b2b, t2, pairTiles);
    eaw_atom1_mm<<<atomTiles, ATHREADS, A_SMEM>>>(FA, b1a, b1b, t1);
    eaw_atom2_mm<<<atomTiles, ATHREADS, A_SMEM>>>(b3a, b3b, t3, out);
}

// round 17
// speedup vs baseline: 1.0305x; 1.0305x over previous
#include <cuda_runtime.h>
#include <cuda_fp16.h>
#include <cstdint>

#define F        128
#define N_ATOMS  8192
#define TILEB    32768        // weight tile: 128 rows * 256B (fp16, swizzled)

#define PTHREADS 256          // pair kernel: 2 CTAs/SM
#define ATHREADS 512          // atom kernels: 1 CTA/SM
#define PTILE    32           // pair tile rows
#define ATILE    64           // atom tile rows

// ---------------------------------------------------------------------------
// Device-global scratch (no allocations allowed)
// ---------------------------------------------------------------------------
__device__ float g_PS[N_ATOMS * F];   // segment-summed pair activations
__device__ float g_AA[N_ATOMS * F];   // atom layer-1 output
// Prepped weights: fp16 (round-to-nearest), B-orientation [n][k], 256B rows,
// XOR-swizzled chunks. 8 tiles of 32768B:
//  0:W2a 1:W2b  2:W1a 3:W1b  4:W3a_c0 5:W3b_c0  6:W3a_c1 7:W3b_c1
__device__ __align__(256) unsigned char g_Wp[8 * TILEB];

// ---- pair kernel SMEM (per CTA, 2 CTAs/SM) ----
//  [0,65536)       W2a, W2b (read once for fragment hoist)
//  [65536,73728)   X buf0 fp16 (32 rows x 256B)
//  [73728,81920)   X buf1
//  [81920,98304)   fp32 stage (32 x 128 fp32 = 16KB)
//  [98304,107008)  epi staging: fp16, 32 rows x 272B (pad -> conflict-free)
//  [107008,108544) bias: ba[128], bb[128], t[128]
#define P_X0     65536
#define P_X1     73728
#define P_STG    81920
#define P_EPI    98304
#define P_BIAS   107008
#define P_SMEM   108544
#define EPI_STRIDE 272        // bytes per epi row (136 halves)

// ---- atom kernel SMEM (1 CTA/SM) ----
#define A_X0     65536
#define A_BIAS   81920
#define A_SMEM   83456

// ---------------------------------------------------------------------------
// PTX helpers
// ---------------------------------------------------------------------------
__device__ __forceinline__ uint32_t smem_u32(const void* p) {
    uint32_t a;
    asm("{ .reg .u64 t; cvta.to.shared.u64 t, %1; cvt.u32.u64 %0, t; }" : "=r"(a) : "l"(p));
    return a;
}
__device__ __forceinline__ void ldmx4(uint32_t* r, uint32_t addr) {
    asm volatile("ldmatrix.sync.aligned.m8n8.x4.shared.b16 {%0,%1,%2,%3}, [%4];"
                 : "=r"(r[0]), "=r"(r[1]), "=r"(r[2]), "=r"(r[3]) : "r"(addr));
}
__device__ __forceinline__ void mma16816(float* d, const uint32_t* a, uint32_t b0, uint32_t b1) {
    asm volatile(
        "mma.sync.aligned.m16n8k16.row.col.f32.f16.f16.f32 "
        "{%0,%1,%2,%3}, {%4,%5,%6,%7}, {%8,%9}, {%0,%1,%2,%3};"
        : "+f"(d[0]), "+f"(d[1]), "+f"(d[2]), "+f"(d[3])
        : "r"(a[0]), "r"(a[1]), "r"(a[2]), "r"(a[3]), "r"(b0), "r"(b1));
}
__device__ __forceinline__ void red_v4(float* addr, float a, float b, float c, float d) {
    asm volatile("red.global.add.v4.f32 [%0], {%1,%2,%3,%4};"
                 :: "l"(addr), "f"(a), "f"(b), "f"(c), "f"(d) : "memory");
}
__device__ __forceinline__ void cpa16(uint32_t saddr, const void* g) {
    asm volatile("cp.async.cg.shared.global [%0], [%1], 16;" :: "r"(saddr), "l"(g));
}
__device__ __forceinline__ void cpa_commit() {
    asm volatile("cp.async.commit_group;" ::: "memory");
}
__device__ __forceinline__ void cpa_wait0() {
    asm volatile("cp.async.wait_group 0;" ::: "memory");
}

// ---------------------------------------------------------------------------
// X element store: fp32 float4 -> fp16 at swizzled (row m, k4).
// i = float4 index: m = i>>5, k4 = (i&31)*4. 256B rows; chunk c at (c^(m&7)).
// ---------------------------------------------------------------------------
union H2U { __half2 h; uint32_t u; };

__device__ __forceinline__ void x_store(char* sm, uint32_t x_off, int i, float4 v) {
    const int m = i >> 5, k4 = (i & 31) << 2;
    const uint32_t sw = (uint32_t)(m << 8) + ((uint32_t)(((k4 >> 3) ^ (m & 7))) << 4)
                      + ((uint32_t)((k4 >> 2) & 1) << 3);
    H2U a, b;
    a.h = __floats2half2_rn(v.x, v.y);
    b.h = __floats2half2_rn(v.z, v.w);
    *(uint2*)(sm + x_off + sw) = make_uint2(a.u, b.u);
}

// ---------------------------------------------------------------------------
// Atom-kernel GEMM core (unchanged): warp patch 32x16, B from smem.
// ---------------------------------------------------------------------------
__device__ __forceinline__ void gemm_core(uint32_t wBase, uint32_t X,
                                          int mBase, int nBase, int r, int q,
                                          float (&accA)[2][2][4], float (&accB)[2][2][4]) {
    const int cA = q >> 1, cB = q & 1;
    const uint32_t aRow0 = (uint32_t)(mBase + r + 8 * (q & 1));
    const uint32_t bRow  = (uint32_t)(nBase + r + 8 * (q >> 1));

    uint32_t Ah[2][2][4];
    uint32_t Ba[2][4], Bb[2][4];

#define LD_K(buf, kc) do {                                                   \
    const uint32_t oA = (uint32_t)(((cA + (kc)) ^ r) << 4);                  \
    ldmx4(Ah[buf][0], X + (aRow0 << 8) + oA);                                \
    ldmx4(Ah[buf][1], X + ((aRow0 + 16) << 8) + oA);                         \
    const uint32_t oB = (bRow << 8) + (uint32_t)(((cB + (kc)) ^ r) << 4);    \
    ldmx4(Ba[buf], wBase + oB);                                              \
    ldmx4(Bb[buf], wBase + 32768 + oB);                                      \
} while (0)

    LD_K(0, 0);
#pragma unroll
    for (int k = 0; k < 8; k++) {
        const int cur = k & 1;
        if (k < 7) LD_K(cur ^ 1, 2 * (k + 1));
#pragma unroll
        for (int mi = 0; mi < 2; mi++)
#pragma unroll
            for (int jj = 0; jj < 2; jj++) {
                mma16816(accA[mi][jj], Ah[cur][mi], Ba[cur][2 * jj], Ba[cur][2 * jj + 1]);
                mma16816(accB[mi][jj], Ah[cur][mi], Bb[cur][2 * jj], Bb[cur][2 * jj + 1]);
            }
    }
#undef LD_K
}

// ---------------------------------------------------------------------------
// Weight prep (+ zero g_PS): fp16 rn, B-orientation, swizzled. 512x256.
// ---------------------------------------------------------------------------
extern "C" __global__ void eaw_prep(const float* __restrict__ W1a, const float* __restrict__ W1b,
                                    const float* __restrict__ W2a, const float* __restrict__ W2b,
                                    const float* __restrict__ W3a, const float* __restrict__ W3b) {
    const int e = blockIdx.x * blockDim.x + threadIdx.x;
    ((float4*)g_PS)[e]          = make_float4(0.f, 0.f, 0.f, 0.f);
    ((float4*)g_PS)[e + 131072] = make_float4(0.f, 0.f, 0.f, 0.f);

    int mat, off;
    if (e < 65536) { mat = e >> 14; off = e & 16383; }
    else           { int e2 = e - 65536; mat = 4 + (e2 >> 15); off = e2 & 32767; }
    const float* W;
    switch (mat) {
        case 0: W = W2a; break; case 1: W = W2b; break;
        case 2: W = W1a; break; case 3: W = W1b; break;
        case 4: W = W3a; break; default: W = W3b; break;
    }
    const int n = off & 127, k = off >> 7;     // W[k][n] at W[off] (coalesced)
    const __half h = __float2half_rn(W[off]);
    const int p = k >> 7, kk = k & 127;
    int tileIdx;
    switch (mat) {
        case 0: tileIdx = 0; break; case 1: tileIdx = 1; break;
        case 2: tileIdx = 2; break; case 3: tileIdx = 3; break;
        case 4: tileIdx = 4 + 2 * p; break;
        default: tileIdx = 5 + 2 * p; break;
    }
    const size_t pos = ((size_t)n << 8) + ((size_t)((kk >> 3) ^ (n & 7)) << 4) + ((size_t)(kk & 7) << 1);
    *(__half*)(g_Wp + (size_t)tileIdx * TILEB + pos) = h;
}

// ---------------------------------------------------------------------------
// Pair branch: persistent, 32-row tiles, 256 threads (8 warps x patch 32x16),
// 2 CTAs/SM, weights hoisted to registers. Epilogue staged in fp16 smem and
// drained with red.v4 (HALF the atomic ops). Two barriers per tile.
// ---------------------------------------------------------------------------
extern "C" __global__ void __launch_bounds__(PTHREADS, 2)
eaw_pair_mm(const float* __restrict__ FP, const int* __restrict__ split,
            const float* __restrict__ b2a, const float* __restrict__ b2b,
            const float* __restrict__ t2, int nTiles) {
    extern __shared__ __align__(1024) char sm[];
    const int tid = threadIdx.x;
    const uint32_t smb = smem_u32(sm);

    {   // weights: 2 tiles (65536B)
        const uint4* src = (const uint4*)g_Wp;
        uint4* dst = (uint4*)sm;
        for (int i = tid; i < 4096; i += PTHREADS) dst[i] = src[i];
    }
    if (tid < 128) {
        ((float*)(sm + P_BIAS))[tid]       = b2a[tid];
        ((float*)(sm + P_BIAS))[128 + tid] = b2b[tid];
        ((float*)(sm + P_BIAS))[256 + tid] = t2[tid];
    }
    __syncthreads();

    const int lane = tid & 31, w = tid >> 5;
    const int nBase = w * 16;                 // 8 warps cover 128 cols
    const int q = lane >> 3, r = lane & 7;
    const float* biasA = (const float*)(sm + P_BIAS);
    const float* biasB = biasA + 128;
    const float* tvv   = biasA + 256;
    const int grid = gridDim.x;

    // hoist ALL weight fragments into registers (once)
    uint32_t Ba[8][4], Bb[8][4];
    {
        const int cB = q & 1;
        const uint32_t bRow = (uint32_t)(nBase + r + 8 * (q >> 1));
#pragma unroll
        for (int k = 0; k < 8; k++) {
            const uint32_t oB = (bRow << 8) + (uint32_t)(((cB + 2 * k) ^ r) << 4);
            ldmx4(Ba[k], smb + oB);
            ldmx4(Bb[k], smb + 32768 + oB);
        }
    }

    const int cA = q >> 1;
    const uint32_t aRow0 = (uint32_t)(r + 8 * (q & 1));
    const uint32_t xOff[2] = {P_X0, P_X1};
    // epilogue store coordinates (per thread): (row, c) pairs
    const int epiR0 = lane >> 2, epiC = nBase + 2 * (lane & 3);
    // drain coordinates: rows (tid>>5)+8*dd, col4 = (tid&31)*4
    const int drRow0 = tid >> 5, drC4 = (tid & 31) << 2;

    // prologue: X(tile0) direct to buf0; stage fetch X(tile0+grid)
    int tile = blockIdx.x;
    {
        const float4* src = (const float4*)(FP + (size_t)tile * (PTILE * F));
#pragma unroll
        for (int qq = 0; qq < 4; qq++) {
            const int i = tid + qq * PTHREADS;
            x_store(sm, P_X0, i, src[i]);
        }
    }
    if (tile + grid < nTiles) {
        const float* src = FP + (size_t)(tile + grid) * (PTILE * F);
#pragma unroll
        for (int qq = 0; qq < 4; qq++) {
            const int sidx = tid + qq * PTHREADS;
            cpa16(smb + P_STG + (uint32_t)sidx * 16, src + (size_t)sidx * 4);
        }
        cpa_commit();
    }
    __syncthreads();

    int b = 0;
    for (; tile < nTiles; tile += grid) {
        // drain-row atom indices (LDG latency hidden under gemm)
        const int* sp = split + tile * PTILE;
        int drAtom[4];
#pragma unroll
        for (int dd = 0; dd < 4; dd++) drAtom[dd] = sp[drRow0 + 8 * dd];

        float accA[2][2][4], accB[2][2][4];
#pragma unroll
        for (int mi = 0; mi < 2; mi++)
#pragma unroll
            for (int jj = 0; jj < 2; jj++)
#pragma unroll
                for (int kq = 0; kq < 4; kq++) { accA[mi][jj][kq] = 0.f; accB[mi][jj][kq] = 0.f; }

        // mainloop: A-ldsm + HMMA only (weights in registers)
        {
            const uint32_t X = smb + xOff[b];
#pragma unroll
            for (int k = 0; k < 8; k++) {
                const uint32_t oA = (uint32_t)(((cA + 2 * k) ^ r) << 4);
                uint32_t A0[4], A1[4];
                ldmx4(A0, X + (aRow0 << 8) + oA);
                ldmx4(A1, X + ((aRow0 + 16) << 8) + oA);
#pragma unroll
                for (int jj = 0; jj < 2; jj++) {
                    mma16816(accA[0][jj], A0, Ba[k][2 * jj], Ba[k][2 * jj + 1]);
                    mma16816(accA[1][jj], A1, Ba[k][2 * jj], Ba[k][2 * jj + 1]);
                    mma16816(accB[0][jj], A0, Bb[k][2 * jj], Bb[k][2 * jj + 1]);
                    mma16816(accB[1][jj], A1, Bb[k][2 * jj], Bb[k][2 * jj + 1]);
                }
            }
        }

        // epilogue: relu(t*ya*yb) -> fp16 epi staging (padded rows)
#pragma unroll
        for (int mi = 0; mi < 2; mi++)
#pragma unroll
            for (int sub = 0; sub < 2; sub++) {
                const int row = 16 * mi + epiR0 + 8 * sub;
#pragma unroll
                for (int jj = 0; jj < 2; jj++) {
                    const int c = epiC + 8 * jj;
                    const float v0 = fmaxf(tvv[c]     * (accA[mi][jj][2 * sub]     + biasA[c])     * (accB[mi][jj][2 * sub]     + biasB[c]),     0.f);
                    const float v1 = fmaxf(tvv[c + 1] * (accA[mi][jj][2 * sub + 1] + biasA[c + 1]) * (accB[mi][jj][2 * sub + 1] + biasB[c + 1]), 0.f);
                    H2U hv; hv.h = __floats2half2_rn(v0, v1);
                    *(uint32_t*)(sm + P_EPI + row * EPI_STRIDE + c * 2) = hv.u;
                }
            }

        const int nt = tile + grid;
        if (nt < nTiles) {
            cpa_wait0();                    // stage holds X(nt) (own bytes)
            const float4* st = (const float4*)(sm + P_STG);
#pragma unroll
            for (int qq = 0; qq < 4; qq++) {
                const int sidx = tid + qq * PTHREADS;
                x_store(sm, xOff[b ^ 1], sidx, st[sidx]);
            }
        }
        __syncthreads();                    // A: publishes epi + Xbuf b^1

        // drain: 4 x red.v4 per thread (coalesced epi reads, conflict-free)
#pragma unroll
        for (int dd = 0; dd < 4; dd++) {
            const int row = drRow0 + 8 * dd;
            const uint2 pk = *(const uint2*)(sm + P_EPI + row * EPI_STRIDE + drC4 * 2);
            H2U u0, u1; u0.u = pk.x; u1.u = pk.y;
            const float2 f0 = __half22float2(u0.h);
            const float2 f1 = __half22float2(u1.h);
            red_v4(g_PS + (size_t)drAtom[dd] * F + drC4, f0.x, f0.y, f1.x, f1.y);
        }
        __syncthreads();                    // B: epi reads done before reuse

        if (nt + grid < nTiles) {
            const float* src = FP + (size_t)(nt + grid) * (PTILE * F);
#pragma unroll
            for (int qq = 0; qq < 4; qq++) {
                const int sidx = tid + qq * PTHREADS;
                cpa16(smb + P_STG + (uint32_t)sidx * 16, src + (size_t)sidx * 4);
            }
            cpa_commit();
        }
        b ^= 1;
    }
}

// ---------------------------------------------------------------------------
// Atom layer 1: g_AA = relu(t1*(FA@W1a+b1a)*(FA@W1b+b1b)). 128 CTAs x 64 rows.
// ---------------------------------------------------------------------------
extern "C" __global__ void __launch_bounds__(ATHREADS, 1)
eaw_atom1_mm(const float* __restrict__ FA,
             const float* __restrict__ b1a, const float* __restrict__ b1b,
             const float* __restrict__ t1) {
    extern __shared__ __align__(1024) char sm[];
    const int tid = threadIdx.x;
    const uint32_t smb = smem_u32(sm);
    {
        const uint4* src = (const uint4*)(g_Wp + 2 * TILEB);
        uint4* dst = (uint4*)sm;
        for (int i = tid; i < 4096; i += ATHREADS) dst[i] = src[i];
    }
    if (tid < 128) {
        ((float*)(sm + A_BIAS))[tid]       = b1a[tid];
        ((float*)(sm + A_BIAS))[128 + tid] = b1b[tid];
        ((float*)(sm + A_BIAS))[256 + tid] = t1[tid];
    }
    {
        const float4* src = (const float4*)(FA + (size_t)blockIdx.x * (ATILE * F));
        float4 xv[4];
#pragma unroll
        for (int qq = 0; qq < 4; qq++) xv[qq] = src[tid + qq * ATHREADS];
#pragma unroll
        for (int qq = 0; qq < 4; qq++) x_store(sm, A_X0, tid + qq * ATHREADS, xv[qq]);
    }
    __syncthreads();

    const int lane = tid & 31, w = tid >> 5;
    const int mBase = (w >> 3) * 32, nBase = (w & 7) * 16;
    const int q = lane >> 3, r = lane & 7;
    const float* biasA = (const float*)(sm + A_BIAS);
    const float* biasB = biasA + 128;
    const float* tvv   = biasA + 256;

    float accA[2][2][4], accB[2][2][4];
#pragma unroll
    for (int mi = 0; mi < 2; mi++)
#pragma unroll
        for (int jj = 0; jj < 2; jj++)
#pragma unroll
            for (int kq = 0; kq < 4; kq++) { accA[mi][jj][kq] = 0.f; accB[mi][jj][kq] = 0.f; }

    gemm_core(smb, smb + A_X0, mBase, nBase, r, q, accA, accB);

    float* base = g_AA + (size_t)blockIdx.x * (ATILE * F);
#pragma unroll
    for (int mi = 0; mi < 2; mi++)
#pragma unroll
        for (int sub = 0; sub < 2; sub++) {
            const int row = mBase + 16 * mi + (lane >> 2) + 8 * sub;
#pragma unroll
            for (int jj = 0; jj < 2; jj++) {
                const int c = nBase + 8 * jj + 2 * (lane & 3);
                float2 v;
                v.x = fmaxf(tvv[c]     * (accA[mi][jj][2 * sub]     + biasA[c])     * (accB[mi][jj][2 * sub]     + biasB[c]),     0.f);
                v.y = fmaxf(tvv[c + 1] * (accA[mi][jj][2 * sub + 1] + biasA[c + 1]) * (accB[mi][jj][2 * sub + 1] + biasB[c + 1]), 0.f);
                *(float2*)(base + (size_t)row * F + c) = v;
            }
        }
}

// ---------------------------------------------------------------------------
// Final layer (K=256, two phases): out = relu(t3*([AA|PS]@W3a+b3a)*(...b)).
// 128 CTAs x 64 rows.
// ---------------------------------------------------------------------------
extern "C" __global__ void __launch_bounds__(ATHREADS, 1)
eaw_atom2_mm(const float* __restrict__ b3a, const float* __restrict__ b3b,
             const float* __restrict__ t3, float* __restrict__ out) {
    extern __shared__ __align__(1024) char sm[];
    const int tid = threadIdx.x;
    const uint32_t smb = smem_u32(sm);
    if (tid < 128) {
        ((float*)(sm + A_BIAS))[tid]       = b3a[tid];
        ((float*)(sm + A_BIAS))[128 + tid] = b3b[tid];
        ((float*)(sm + A_BIAS))[256 + tid] = t3[tid];
    }
    const int lane = tid & 31, w = tid >> 5;
    const int mBase = (w >> 3) * 32, nBase = (w & 7) * 16;
    const int q = lane >> 3, r = lane & 7;
    const float* biasA = (const float*)(sm + A_BIAS);
    const float* biasB = biasA + 128;
    const float* tvv   = biasA + 256;

    float accA[2][2][4], accB[2][2][4];
#pragma unroll
    for (int mi = 0; mi < 2; mi++)
#pragma unroll
        for (int jj = 0; jj < 2; jj++)
#pragma unroll
            for (int kq = 0; kq < 4; kq++) { accA[mi][jj][kq] = 0.f; accB[mi][jj][kq] = 0.f; }

#pragma unroll 1
    for (int p = 0; p < 2; p++) {
        if (p) __syncthreads();             // previous phase's smem reads done
        {
            const uint4* src = (const uint4*)(g_Wp + (size_t)(4 + 2 * p) * TILEB);
            uint4* dst = (uint4*)sm;
            for (int i = tid; i < 4096; i += ATHREADS) dst[i] = src[i];
        }
        {
            const float4* src = (const float4*)((p == 0 ? g_AA : g_PS) + (size_t)blockIdx.x * (ATILE * F));
            float4 xv[4];
#pragma unroll
            for (int qq = 0; qq < 4; qq++) xv[qq] = src[tid + qq * ATHREADS];
#pragma unroll
            for (int qq = 0; qq < 4; qq++) x_store(sm, A_X0, tid + qq * ATHREADS, xv[qq]);
        }
        __syncthreads();
        gemm_core(smb, smb + A_X0, mBase, nBase, r, q, accA, accB);
    }

    float* base = out + (size_t)blockIdx.x * (ATILE * F);
#pragma unroll
    for (int mi = 0; mi < 2; mi++)
#pragma unroll
        for (int sub = 0; sub < 2; sub++) {
            const int row = mBase + 16 * mi + (lane >> 2) + 8 * sub;
#pragma unroll
            for (int jj = 0; jj < 2; jj++) {
                const int c = nBase + 8 * jj + 2 * (lane & 3);
                float2 v;
                v.x = fmaxf(tvv[c]     * (accA[mi][jj][2 * sub]     + biasA[c])     * (accB[mi][jj][2 * sub]     + biasB[c]),     0.f);
                v.y = fmaxf(tvv[c + 1] * (accA[mi][jj][2 * sub + 1] + biasA[c + 1]) * (accB[mi][jj][2 * sub + 1] + biasB[c + 1]), 0.f);
                *(float2*)(base + (size_t)row * F + c) = v;
            }
        }
}

// ---------------------------------------------------------------------------
// Launch
// ---------------------------------------------------------------------------
extern "C" void kernel_launch(void* const* d_in, const int* in_sizes, int n_in,
                              void* d_out, int out_size) {
    const float* FA  = (const float*)d_in[0];
    const float* FP  = (const float*)d_in[1];
    const int*   sp  = (const int*)  d_in[2];
    const float* W1a = (const float*)d_in[3];
    const float* b1a = (const float*)d_in[4];
    const float* W1b = (const float*)d_in[5];
    const float* b1b = (const float*)d_in[6];
    const float* t1  = (const float*)d_in[7];
    const float* W2a = (const float*)d_in[8];
    const float* b2a = (const float*)d_in[9];
    const float* W2b = (const float*)d_in[10];
    const float* b2b = (const float*)d_in[11];
    const float* t2  = (const float*)d_in[12];
    const float* W3a = (const float*)d_in[13];
    const float* b3a = (const float*)d_in[14];
    const float* W3b = (const float*)d_in[15];
    const float* b3b = (const float*)d_in[16];
    const float* t3  = (const float*)d_in[17];
    float* out = (float*)d_out;

    const int nPairs    = in_sizes[1] / F;              // 524288
    const int pairTiles = nPairs / PTILE;               // 16384
    const int atomTiles = (in_sizes[0] / F) / ATILE;    // 128

    cudaFuncSetAttribute(eaw_pair_mm,  cudaFuncAttributeMaxDynamicSharedMemorySize, P_SMEM);
    cudaFuncSetAttribute(eaw_atom1_mm, cudaFuncAttributeMaxDynamicSharedMemorySize, A_SMEM);
    cudaFuncSetAttribute(eaw_atom2_mm, cudaFuncAttributeMaxDynamicSharedMemorySize, A_SMEM);

    int nsm = 148;
    cudaDeviceGetAttribute(&nsm, cudaDevAttrMultiProcessorCount, 0);

    eaw_prep<<<512, 256>>>(W1a, W1b, W2a, W2b, W3a, W3b);
    eaw_pair_mm<<<2 * nsm, PTHREADS, P_SMEM>>>(FP, sp, b2a, b2b, t2, pairTiles);
    eaw_atom1_mm<<<atomTiles, ATHREADS, A_SMEM>>>(FA, b1a, b1b, t1);
    eaw_atom2_mm<<<atomTiles, ATHREADS, A_SMEM>>>(b3a, b3b, t3, out);
}